// round 1
// baseline (speedup 1.0000x reference)
#include <cuda_runtime.h>

#define Bsz 8
#define Cch 64
#define Hh  128
#define Wwi 128
#define Och 64
#define HW  (Hh*Wwi)

#define TILE_ROWS 4
#define THREADS   512

// smem layout (floats):
//  Wt padded: [c=64][k=9][og=4][18]  (16 used + 2 pad for bank-skew) = 41472
//  gs tile:   [k=9][rl=4][128]                                        = 4608
//  x tile:    [6][132]                                                = 792
#define WT_PAD_SZ (64*9*4*18)
#define GS_SZ     (9*TILE_ROWS*128)
#define XS_SZ     (6*132)
#define SMEM_FLOATS (WT_PAD_SZ + GS_SZ + XS_SZ)

__device__ float d_wt[Cch*9*Och];   // transposed weight: [c][k][o]

extern __shared__ float smem[];

__device__ __forceinline__ float tanh_fast(float v) {
    float y;
    asm("tanh.approx.f32 %0, %1;" : "=f"(y) : "f"(v));
    return y;
}

__device__ __forceinline__ unsigned long long pack2(float a) {
    unsigned long long r;
    asm("mov.b64 %0, {%1, %1};" : "=l"(r) : "f"(a));
    return r;
}

__device__ __forceinline__ void ffma2(unsigned long long &acc,
                                      unsigned long long a,
                                      unsigned long long w) {
    asm("fma.rn.f32x2 %0, %1, %2, %0;" : "+l"(acc) : "l"(a), "l"(w));
}

__device__ __forceinline__ float2 unpack2(unsigned long long v) {
    float2 r;
    asm("mov.b64 {%0, %1}, %2;" : "=f"(r.x), "=f"(r.y) : "l"(v));
    return r;
}

// One-time weight transpose: w[o][c][k] (o*576 + c*9 + k) -> d_wt[c][k][o]
__global__ void paka_transpose_w(const float* __restrict__ w) {
    int idx = blockIdx.x * blockDim.x + threadIdx.x;
    if (idx < Cch*9*Och) {
        int o  = idx & 63;
        int ck = idx >> 6;                 // c*9 + k
        d_wt[idx] = w[o * (Cch*9) + ck];
    }
}

__global__ void __launch_bounds__(THREADS, 1)
paka_kernel(const float* __restrict__ x,
            const float* __restrict__ gc,
            const float* __restrict__ gsp,
            float* __restrict__ out)
{
    float* Wt  = smem;                     // WT_PAD_SZ
    float* gss = smem + WT_PAD_SZ;         // GS_SZ
    float* xs  = gss + GS_SZ;              // XS_SZ

    const int tid = threadIdx.x;
    const int b   = blockIdx.y;
    const int r0  = blockIdx.x * TILE_ROWS;

    // ---- stage weight (coalesced read from d_wt, skewed write) ----
    #pragma unroll 4
    for (int v = tid; v < Cch*9*Och; v += THREADS) {
        int o  = v & 63;
        int ck = v >> 6;                   // c*9 + k
        int dst = ck * 72 + (o >> 4) * 18 + (o & 15);
        Wt[dst] = d_wt[v];
    }
    // ---- stage gs tile ----
    for (int i = tid; i < GS_SZ; i += THREADS) {
        int col = i & 127;
        int krl = i >> 7;                  // k*4 + rl
        int k  = krl >> 2;
        int rl = krl & 3;
        gss[i] = gsp[(((size_t)b*9 + k)*Hh + (r0 + rl))*Wwi + col];
    }

    const int og   = tid & 3;              // 16-output group
    const int pg   = tid >> 2;             // 0..127 pixel group
    const int rl   = pg >> 5;              // 0..3
    const int col0 = (pg & 31) << 2;       // 0..124 step 4
    const int r    = r0 + rl;

    unsigned long long acc[4][8];
    #pragma unroll
    for (int p = 0; p < 4; ++p)
        #pragma unroll
        for (int j = 0; j < 8; ++j) acc[p][j] = 0ull;

    const float* x_base  = x  + (size_t)b*Cch*HW;
    const float* gc_base = gc + (size_t)b*Cch*HW + (size_t)r*Wwi + col0;

    for (int c = 0; c < Cch; ++c) {
        __syncthreads();   // previous iteration's xs reads complete
        // ---- stage x halo tile: rows r0-1..r0+4, cols -1..130 ----
        #pragma unroll
        for (int i = tid; i < XS_SZ; i += THREADS) {
            int row = i / 132;
            int j   = i - row * 132;
            int gh  = r0 - 1 + row;
            int gw  = j - 1;
            float v = 0.f;
            if ((unsigned)gh < Hh && (unsigned)gw < Wwi)
                v = x_base[(size_t)c*HW + gh*Wwi + gw];
            xs[i] = v;
        }
        const float4 gcv = *(const float4*)(gc_base + (size_t)c*HW);
        __syncthreads();

        const float* wck = Wt + c * (9*72) + og * 18;

        #pragma unroll
        for (int di = 0; di < 3; ++di) {
            const float* xr = xs + (rl + di) * 132 + col0;
            const float4 xv4 = *(const float4*)xr;
            const float2 xv2 = *(const float2*)(xr + 4);
            const float xrow[6] = {xv4.x, xv4.y, xv4.z, xv4.w, xv2.x, xv2.y};
            #pragma unroll
            for (int dj = 0; dj < 3; ++dj) {
                const int k = di*3 + dj;
                const float4 gsv = *(const float4*)(gss + (k*TILE_ROWS + rl)*128 + col0);
                const float t0 = tanh_fast(gcv.x + gsv.x);
                const float t1 = tanh_fast(gcv.y + gsv.y);
                const float t2 = tanh_fast(gcv.z + gsv.z);
                const float t3 = tanh_fast(gcv.w + gsv.w);
                unsigned long long ap0 = pack2(fmaf(xrow[dj+0], t0, xrow[dj+0]));
                unsigned long long ap1 = pack2(fmaf(xrow[dj+1], t1, xrow[dj+1]));
                unsigned long long ap2 = pack2(fmaf(xrow[dj+2], t2, xrow[dj+2]));
                unsigned long long ap3 = pack2(fmaf(xrow[dj+3], t3, xrow[dj+3]));
                const unsigned long long* wp =
                    (const unsigned long long*)(wck + k * 72);
                #pragma unroll
                for (int j = 0; j < 8; ++j) {
                    const unsigned long long wj = wp[j];
                    ffma2(acc[0][j], ap0, wj);
                    ffma2(acc[1][j], ap1, wj);
                    ffma2(acc[2][j], ap2, wj);
                    ffma2(acc[3][j], ap3, wj);
                }
            }
        }
    }

    // ---- store: p-vectorized float4 per output channel ----
    float* outp = out + ((size_t)b*Och*Hh + r)*Wwi + col0;
    #pragma unroll
    for (int j = 0; j < 8; ++j) {
        const float2 v0 = unpack2(acc[0][j]);
        const float2 v1 = unpack2(acc[1][j]);
        const float2 v2 = unpack2(acc[2][j]);
        const float2 v3 = unpack2(acc[3][j]);
        const int o0 = og*16 + 2*j;
        const float4 lo = make_float4(v0.x, v1.x, v2.x, v3.x);
        const float4 hi = make_float4(v0.y, v1.y, v2.y, v3.y);
        *(float4*)(outp + (size_t)o0     * HW) = lo;
        *(float4*)(outp + (size_t)(o0+1) * HW) = hi;
    }
}

extern "C" void kernel_launch(void* const* d_in, const int* in_sizes, int n_in,
                              void* d_out, int out_size) {
    const float* x  = (const float*)d_in[0];
    const float* gc = (const float*)d_in[1];
    const float* gs = (const float*)d_in[2];
    const float* w  = (const float*)d_in[3];
    float* out = (float*)d_out;

    paka_transpose_w<<<(Cch*9*Och + 1023)/1024, 1024>>>(w);

    const size_t smem_bytes = SMEM_FLOATS * sizeof(float);
    static bool attr_set = false;
    (void)cudaFuncSetAttribute(paka_kernel,
                               cudaFuncAttributeMaxDynamicSharedMemorySize,
                               (int)smem_bytes);
    (void)attr_set;

    dim3 grid(Hh / TILE_ROWS, Bsz);   // (32, 8)
    paka_kernel<<<grid, THREADS, smem_bytes>>>(x, gc, gs, out);
}